// round 9
// baseline (speedup 1.0000x reference)
#include <cuda_runtime.h>
#include <cstdint>

// ---------------------------------------------------------------------------
// HausdorffLoss: B=8, N=M=4096, 3-D points. Exact hierarchical pruning.
//
// H_z = max_n min_m d(n,m). Lower bound from full scans of rows [0,512);
// rows [512,4096) probed over cols [0,512); rows whose probe-min < bound
// cannot be the argmax (true min <= probe min < bound <= H) -> pruned.
// Survivors get exact full rescans in K3. Result bit-identical across
// graph replays (survivor SET is a deterministic function of the
// deterministic keys/bound; max over the set is order-independent).
//
// K1 grid (120, 16): 64 A-blocks (bound rows, 32 col-splits) + 56 B-blocks
// (probe rows, 4 col-splits), each 256 rows x 128 cols. Per-z ticket ->
// finalizer builds bound + worklist + resets keys.
// K3 grid (8, 8, 16): col-split 8 x 512 cols; bx strides survivor list in
// 256-row chunks; keys -> per-z max -> per-batch max -> sum; all state reset.
// ---------------------------------------------------------------------------

#define NPOINT 4096
#define T      128
#define NGRP   16
#define NBOUND 512                   // rows with full scans in K1
#define NPROBE (NPOINT - NBOUND)     // 3584 probed rows
#define PCOLS  512                   // probe column count
#define K1BLK  120                   // 64 A + 56 B blocks per group
#define K3BLK  64                    // 8 x 8 blocks per group in K3

#define FMA2(d, a, b, c) \
    asm("fma.rn.f32x2 %0, %1, %2, %3;" : "=l"(d) : "l"(a), "l"(b), "l"(c))
#define PACK2(o, x) \
    asm("mov.b64 %0, {%1, %1};" : "=l"(o) : "f"(x))
#define UNPACK2(lo, hi, v) \
    asm("mov.b64 {%0, %1}, %2;" : "=f"(lo), "=f"(hi) : "l"(v))

// Monotone map: smaller float <=> LARGER unsigned key (row min == atomicMax).
// Every real float maps to key > 0, so 0 is the identity/reset state.
__device__ __forceinline__ unsigned map_min(float f) {
    unsigned u = __float_as_uint(f);
    return ((int)u < 0) ? u : (~u & 0x7FFFFFFFu);
}
__device__ __forceinline__ float unmap_min(unsigned s) {
    return ((int)s < 0) ? __uint_as_float(s)
                        : __uint_as_float(~s & 0x7FFFFFFFu);
}

__device__ unsigned g_cmb[NGRP][NPOINT];   // row-min keys (reset 0)
__device__ int      g_grp[NGRP];           // per-group tickets (reset 0)
__device__ float    g_bound[NGRP];         // per-(b,dir) bound/answer (reset 0)
__device__ int      g_cnt[NGRP];           // survivor counts (reset 0)
__device__ int      g_list[NGRP][NPROBE];  // survivor row lists
__device__ int      g_done;                // global ticket (reset 0)

// --- shared inner loop: RN=2 rows x TMv cols through an f32x2 tile ----------
// tile entry pair j: [2j]   = {-2y0[e],-2y0[o],-2y1[e],-2y1[o]}
//                    [2j+1] = {-2y2[e],-2y2[o],  y2[e],  y2[o]}
template <int TMv>
__device__ __forceinline__ void fill_tile(ulonglong2* sAB, const float* cols,
                                          int c0, int tid) {
#pragma unroll
    for (int ii = 0; ii < TMv / T; ii++) {
        const int idx = ii * T + tid;
        const float* pc = cols + (size_t)(c0 + idx) * 3;
        const float y0 = pc[0], y1 = pc[1], y2 = pc[2];
        const float ysq = y0 * y0 + y1 * y1 + y2 * y2;
        const int j = idx >> 1, l = idx & 1;
        float* A  = reinterpret_cast<float*>(&sAB[2 * j]);
        float* Bv = reinterpret_cast<float*>(&sAB[2 * j + 1]);
        A[l]      = -2.0f * y0;
        A[2 + l]  = -2.0f * y1;
        Bv[l]     = -2.0f * y2;
        Bv[2 + l] = ysq;
    }
}

template <int TMv>
__device__ __forceinline__ void scan_tile(const ulonglong2* sAB,
                                          const unsigned long long* px0,
                                          const unsigned long long* px1,
                                          const unsigned long long* px2,
                                          float* rmE, float* rmO) {
    const ulonglong2* sp = sAB;
#pragma unroll 8
    for (int j = 0; j < TMv / 2; j++, sp += 2) {
        const ulonglong2 va = sp[0];
        const ulonglong2 vb = sp[1];
#pragma unroll
        for (int r = 0; r < 2; r++) {
            unsigned long long t0r, t1r, acc;
            FMA2(t0r, px2[r], vb.x, vb.y);
            FMA2(t1r, px1[r], va.y, t0r);
            FMA2(acc, px0[r], va.x, t1r);
            float lo, hi;
            UNPACK2(lo, hi, acc);
            rmE[r] = fminf(rmE[r], lo);
            rmO[r] = fminf(rmO[r], hi);
        }
    }
}

// ---------------------------------------------------------------------------
// K1: bound rows (full) + probe rows (512 cols), then per-z finalize.
// ---------------------------------------------------------------------------
__global__ void __launch_bounds__(T, 8)
hd_phase1(const float* __restrict__ p1, const float* __restrict__ p2) {
    const int tid = threadIdx.x;
    const int z   = blockIdx.y;
    const int b   = z >> 1;
    const int dir = z & 1;
    const float* rows = (dir == 0 ? p1 : p2) + (size_t)b * NPOINT * 3;
    const float* cols = (dir == 0 ? p2 : p1) + (size_t)b * NPOINT * 3;

    const int bx = blockIdx.x;
    int rb, cs;
    if (bx < 64) { rb = bx >> 5;            cs = bx & 31; }  // A: rows [0,512)
    else         { rb = 2 + ((bx - 64) >> 2); cs = (bx - 64) & 3; } // B
    const int rowbase = rb * 256;
    const int c0      = cs * 128;

    unsigned long long px0[2], px1[2], px2[2];
    float xsq[2], rmE[2], rmO[2];
#pragma unroll
    for (int r = 0; r < 2; r++) {
        const int n = rowbase + r * T + tid;
        const float* pr = rows + (size_t)n * 3;
        const float a0 = pr[0], a1 = pr[1], a2 = pr[2];
        xsq[r] = a0 * a0 + a1 * a1 + a2 * a2;
        PACK2(px0[r], a0); PACK2(px1[r], a1); PACK2(px2[r], a2);
        rmE[r] = 3.4e38f; rmO[r] = 3.4e38f;
    }

    __shared__ ulonglong2 sAB[128];
    __shared__ unsigned   sred[T / 32];
    __shared__ float      s_bound;
    fill_tile<128>(sAB, cols, c0, tid);
    __syncthreads();
    scan_tile<128>(sAB, px0, px1, px2, rmE, rmO);

#pragma unroll
    for (int r = 0; r < 2; r++) {
        const int n = rowbase + r * T + tid;
        atomicMax(&g_cmb[z][n], map_min(xsq[r] + fminf(rmE[r], rmO[r])));
    }
    __threadfence();
    __syncthreads();

    __shared__ int s_last;
    if (tid == 0) s_last = (atomicAdd(&g_grp[z], 1) == K1BLK - 1);
    __syncthreads();
    if (!s_last) return;
    __threadfence();

    // bound_z = max over rows [0,512) of their full min.
    unsigned kmin = 0xFFFFFFFFu;
    for (int i = tid; i < NBOUND; i += T) kmin = min(kmin, g_cmb[z][i]);
#pragma unroll
    for (int off = 16; off > 0; off >>= 1)
        kmin = min(kmin, __shfl_xor_sync(0xffffffffu, kmin, off));
    if ((tid & 31) == 0) sred[tid >> 5] = kmin;
    __syncthreads();
    if (tid == 0) {
        unsigned km = sred[0];
#pragma unroll
        for (int w = 1; w < T / 32; w++) km = min(km, sred[w]);
        s_bound = fmaxf(unmap_min(km), 0.0f);
        g_bound[z] = s_bound;
    }
    __syncthreads();
    const float bnd = s_bound;

    // Worklist: probe rows whose 512-col min might still exceed the bound.
    for (int i = NBOUND + tid; i < NPOINT; i += T) {
        if (unmap_min(g_cmb[z][i]) >= bnd) {
            const int p = atomicAdd(&g_cnt[z], 1);
            g_list[z][p] = i;
        }
    }
    // Reset keys (row i touched only by tid == i % T in both loops: safe).
    for (int i = tid; i < NPOINT; i += T) g_cmb[z][i] = 0u;
    if (tid == 0) g_grp[z] = 0;
}

// ---------------------------------------------------------------------------
// K3: exact full rescans of survivors, per-z max, per-batch max, final sum.
// ---------------------------------------------------------------------------
__global__ void __launch_bounds__(T, 8)
hd_phase2(const float* __restrict__ p1, const float* __restrict__ p2,
          float* __restrict__ out, int nb) {
    const int tid = threadIdx.x;
    const int z   = blockIdx.z;
    const int b   = z >> 1;
    const int dir = z & 1;
    const float* rows = (dir == 0 ? p1 : p2) + (size_t)b * NPOINT * 3;
    const float* cols = (dir == 0 ? p2 : p1) + (size_t)b * NPOINT * 3;

    __shared__ ulonglong2 sAB[512];
    __shared__ unsigned   sred[T / 32];
    const int cnt = g_cnt[z];
    fill_tile<512>(sAB, cols, blockIdx.y * 512, tid);
    __syncthreads();

    for (int base = blockIdx.x * 256; base < cnt; base += 8 * 256) {
        int rrow[2] = {-1, -1};
        unsigned long long px0[2], px1[2], px2[2];
        float xsq[2], rmE[2], rmO[2];
#pragma unroll
        for (int r = 0; r < 2; r++) {
            const int li = base + r * T + tid;
            if (li < cnt) rrow[r] = g_list[z][li];
            const float* pr = rows + (size_t)(rrow[r] < 0 ? 0 : rrow[r]) * 3;
            const float a0 = pr[0], a1 = pr[1], a2 = pr[2];
            xsq[r] = a0 * a0 + a1 * a1 + a2 * a2;
            PACK2(px0[r], a0); PACK2(px1[r], a1); PACK2(px2[r], a2);
            rmE[r] = 3.4e38f; rmO[r] = 3.4e38f;
        }
        scan_tile<512>(sAB, px0, px1, px2, rmE, rmO);
#pragma unroll
        for (int r = 0; r < 2; r++)
            if (rrow[r] >= 0)
                atomicMax(&g_cmb[z][rrow[r]],
                          map_min(xsq[r] + fminf(rmE[r], rmO[r])));
    }
    __threadfence();
    __syncthreads();

    __shared__ int s_last;
    if (tid == 0) s_last = (atomicAdd(&g_grp[z], 1) == K3BLK - 1);
    __syncthreads();
    if (!s_last) return;
    __threadfence();

    // Per-z: max over survivors' full mins; reset touched keys.
    unsigned kmin = 0xFFFFFFFFu;
    for (int i = tid; i < cnt; i += T) {
        const int r = g_list[z][i];
        kmin = min(kmin, g_cmb[z][r]);
        g_cmb[z][r] = 0u;
    }
#pragma unroll
    for (int off = 16; off > 0; off >>= 1)
        kmin = min(kmin, __shfl_xor_sync(0xffffffffu, kmin, off));
    if ((tid & 31) == 0) sred[tid >> 5] = kmin;
    __syncthreads();

    if (tid == 0) {
        if (cnt > 0) {
            unsigned km = sred[0];
#pragma unroll
            for (int w = 1; w < T / 32; w++) km = min(km, sred[w]);
            const float m = fmaxf(unmap_min(km), 0.0f);
            atomicMax(reinterpret_cast<int*>(&g_bound[z]), __float_as_int(m));
        }
        g_cnt[z] = 0;
        g_grp[z] = 0;
        __threadfence();
        if (atomicAdd(&g_done, 1) == NGRP - 1) {
            __threadfence();
            float s = 0.0f;
            for (int i = 0; i < nb; i++) {
                s += fmaxf(g_bound[2 * i], g_bound[2 * i + 1]);
                g_bound[2 * i] = 0.0f;
                g_bound[2 * i + 1] = 0.0f;
            }
            out[0] = s;
            __threadfence();
            atomicExch(&g_done, 0);
        }
    }
}

extern "C" void kernel_launch(void* const* d_in, const int* in_sizes, int n_in,
                              void* d_out, int out_size) {
    const float* p1 = (const float*)d_in[0];
    const float* p2 = (const float*)d_in[1];
    float* out = (float*)d_out;

    const int B = in_sizes[0] / (NPOINT * 3);

    dim3 g1(K1BLK, B * 2);
    hd_phase1<<<g1, T>>>(p1, p2);

    dim3 g2(8, 8, B * 2);
    hd_phase2<<<g2, T>>>(p1, p2, out, B);
}

// round 12
// speedup vs baseline: 1.3287x; 1.3287x over previous
#include <cuda_runtime.h>
#include <cstdint>

// ---------------------------------------------------------------------------
// HausdorffLoss: B=8, N=M=4096, 3-D points. Single fused dense kernel.
// d[b,n,m] = x2[n] + y2[m] - 2*dot(x_n, y_m)
// out = sum_b max( max_n min_m d, max_m min_n d )
//
// Round-10: round-5 dense machinery with fine-grained blocks for continuous
// backfill. grid (8, 32, 16) = 4096 blocks (T=128, RN=4 -> 512 rows x
// 128-col slice, 2KB tile). 64 regs -> 8 blocks/SM; small blocks keep all
// SMs at capacity until the very end (no ragged second wave).
// Cross-block per-row min via order-inverted-key atomicMax (identity 0).
// Group ticket -> group max -> per-batch atomicMax -> global ticket ->
// final sum. All global state reset each call (graph-replay invariant).
// ---------------------------------------------------------------------------

#define NPOINT 4096
#define T      128                 // threads per block
#define RN     4                   // rows per thread
#define BN     (T * RN)            // 512 rows per block
#define ROWB   (NPOINT / BN)       // 8 row-blocks
#define CS     32                  // column splits
#define CPB    (NPOINT / CS)       // 128 cols per block
#define TM     CPB                 // tile = whole slice (2KB)
#define NGRP   16                  // B*2 (b,dir) groups
#define GBLK   (ROWB * CS)         // blocks per group = 256

#define FMA2(d, a, b, c) \
    asm("fma.rn.f32x2 %0, %1, %2, %3;" : "=l"(d) : "l"(a), "l"(b), "l"(c))
#define PACK2(o, x) \
    asm("mov.b64 %0, {%1, %1};" : "=l"(o) : "f"(x))
#define UNPACK2(lo, hi, v) \
    asm("mov.b64 {%0, %1}, %2;" : "=f"(lo), "=f"(hi) : "l"(v))

// Monotone map: smaller float <=> LARGER unsigned key (row min == atomicMax).
// Every real float maps to key > 0, so 0 is the identity/reset state.
__device__ __forceinline__ unsigned map_min(float f) {
    unsigned u = __float_as_uint(f);
    return ((int)u < 0) ? u : (~u & 0x7FFFFFFFu);
}
__device__ __forceinline__ float unmap_min(unsigned s) {
    return ((int)s < 0) ? __uint_as_float(s)
                        : __uint_as_float(~s & 0x7FFFFFFFu);
}

__device__ unsigned g_cmb[NGRP][NPOINT];  // combined row-min keys (reset 0)
__device__ int      g_grp[NGRP];          // per-group tickets (reset 0)
__device__ float    g_bmax[16];           // per-batch max >= 0 (reset 0)
__device__ int      g_done;               // finalizer ticket (reset 0)

__global__ void __launch_bounds__(T, 8)
hd_main(const float* __restrict__ p1, const float* __restrict__ p2,
        float* __restrict__ out, int nb) {
    const int tid = threadIdx.x;
    const int z   = blockIdx.z;          // b*2 + dir
    const int b   = z >> 1;
    const int dir = z & 1;

    const float* rows = (dir == 0 ? p1 : p2) + (size_t)b * NPOINT * 3;
    const float* cols = (dir == 0 ? p2 : p1) + (size_t)b * NPOINT * 3;

    // Per-thread row points, coords broadcast-packed for f32x2.
    unsigned long long px0[RN], px1[RN], px2[RN];
    float xsq[RN], rmE[RN], rmO[RN];

#pragma unroll
    for (int r = 0; r < RN; r++) {
        const int n = blockIdx.x * BN + r * T + tid;
        const float* pr = rows + (size_t)n * 3;
        const float a0 = pr[0], a1 = pr[1], a2 = pr[2];
        xsq[r] = a0 * a0 + a1 * a1 + a2 * a2;
        PACK2(px0[r], a0);
        PACK2(px1[r], a1);
        PACK2(px2[r], a2);
        rmE[r] = 3.4e38f;
        rmO[r] = 3.4e38f;
    }

    // Shared tile: col pair j -> entry 2j   = {-2y0[e],-2y0[o],-2y1[e],-2y1[o]}
    //                            entry 2j+1 = {-2y2[e],-2y2[o],  y2[e],  y2[o]}
    __shared__ ulonglong2 sAB[TM];
    __shared__ unsigned   sred[T / 32];

    {
        const int idx = tid;             // TM == T: one point per thread
        const float* pc = cols + (size_t)(blockIdx.y * CPB + idx) * 3;
        const float y0 = pc[0], y1 = pc[1], y2 = pc[2];
        const float ysq = y0 * y0 + y1 * y1 + y2 * y2;
        const int j = idx >> 1, l = idx & 1;
        float* A  = reinterpret_cast<float*>(&sAB[2 * j]);
        float* Bv = reinterpret_cast<float*>(&sAB[2 * j + 1]);
        A[l]      = -2.0f * y0;
        A[2 + l]  = -2.0f * y1;
        Bv[l]     = -2.0f * y2;
        Bv[2 + l] = ysq;
    }
    __syncthreads();

    const ulonglong2* sp = sAB;
#pragma unroll 8
    for (int j = 0; j < TM / 2; j++, sp += 2) {
        const ulonglong2 va = sp[0];
        const ulonglong2 vb = sp[1];
#pragma unroll
        for (int r = 0; r < RN; r++) {
            unsigned long long t0r, t1r, acc;
            FMA2(t0r, px2[r], vb.x, vb.y);   // -2*x2*y2 + y^2
            FMA2(t1r, px1[r], va.y, t0r);    // + -2*x1*y1
            FMA2(acc, px0[r], va.x, t1r);    // + -2*x0*y0
            float lo, hi;
            UNPACK2(lo, hi, acc);
            rmE[r] = fminf(rmE[r], lo);
            rmO[r] = fminf(rmO[r], hi);
        }
    }

    // Combine this slice's row mins into the global per-row key array.
#pragma unroll
    for (int r = 0; r < RN; r++) {
        const int n = blockIdx.x * BN + r * T + tid;
        const float d = xsq[r] + fminf(rmE[r], rmO[r]);
        atomicMax(&g_cmb[z][n], map_min(d));
    }
    __threadfence();
    __syncthreads();

    // Group ticket: last of the GBLK blocks in this (b,dir) finalizes.
    __shared__ int s_last;
    if (tid == 0)
        s_last = (atomicAdd(&g_grp[z], 1) == GBLK - 1);
    __syncthreads();
    if (!s_last) return;
    __threadfence();

    // Group finalize: max over rows of row-min == unmap(min over keys).
    unsigned kmin = 0xFFFFFFFFu;
    for (int i = tid; i < NPOINT; i += T) {
        kmin = min(kmin, g_cmb[z][i]);
        g_cmb[z][i] = 0u;                       // reset for next replay
    }
#pragma unroll
    for (int off = 16; off > 0; off >>= 1)
        kmin = min(kmin, __shfl_xor_sync(0xffffffffu, kmin, off));
    if ((tid & 31) == 0) sred[tid >> 5] = kmin;
    __syncthreads();

    if (tid == 0) {
        unsigned km = sred[0];
#pragma unroll
        for (int w = 1; w < T / 32; w++) km = min(km, sred[w]);
        float m = fmaxf(unmap_min(km), 0.0f);   // true max > 0
        atomicMax(reinterpret_cast<int*>(&g_bmax[b]), __float_as_int(m));
        g_grp[z] = 0;                           // reset group ticket
        __threadfence();
        if (atomicAdd(&g_done, 1) == NGRP - 1) {
            __threadfence();
            float s = 0.0f;
            for (int i = 0; i < nb; i++) {
                s += g_bmax[i];
                g_bmax[i] = 0.0f;               // reset
            }
            out[0] = s;
            __threadfence();
            atomicExch(&g_done, 0);             // reset
        }
    }
}

extern "C" void kernel_launch(void* const* d_in, const int* in_sizes, int n_in,
                              void* d_out, int out_size) {
    const float* p1 = (const float*)d_in[0];
    const float* p2 = (const float*)d_in[1];
    float* out = (float*)d_out;

    const int B = in_sizes[0] / (NPOINT * 3);
    dim3 grid(ROWB, CS, B * 2);
    hd_main<<<grid, T>>>(p1, p2, out, B);
}